// round 6
// baseline (speedup 1.0000x reference)
#include <cuda_runtime.h>

// out[b,c] = exp( sum_s x[b, chunk_map[c,s]] * wSupp[c,s] )
// B=4096, NCLASS=1000, NSUPP=64, NCHUNK=4096

#define NCLASS 1000
#define NSUPP  64
#define NCHUNK 4096
#define BATCH  4096
#define NB     4       // batch rows per CTA (64 KB tile -> 3 CTAs/SM)
#define THREADS 512

// Packed (idx, w) pairs, transposed to [s2][class] so the hot loop's LDG is
// coalesced across lanes (lane = class). Each int4 holds 2 slots.
//
// Conflict-free schedule: an LDS.128 phase is 8 lanes = 8 consecutive
// classes. At slot p, class c reads bank group (p + c) & 7 when possible:
// each entry of group g = idx&7 goes to a slot p ≡ (g - c) (mod 8). Since
// residues are disjoint across groups, pass-1 placement is closed-form;
// overflow entries (group count > 8) spill into leftover slots.
__device__ int4 g_packed[(NSUPP / 2) * NCLASS];

__global__ void pack_kernel(const float* __restrict__ w,
                            const int* __restrict__ cmap) {
    int c = blockIdx.x * blockDim.x + threadIdx.x;
    if (c >= NCLASS) return;

    const int*   row  = cmap + c * NSUPP;
    const float* wrow = w + c * NSUPP;

    // group counts, 8 counters x 8 bits packed in one u64 (no local arrays)
    unsigned long long cnt = 0ull;
#pragma unroll
    for (int e = 0; e < NSUPP; ++e)
        cnt += 1ull << ((row[e] & 7) * 8);

    int2* outp = (int2*)g_packed;
    unsigned long long cur = 0ull;   // running per-group counters
    int spillrank = 0;

    for (int e = 0; e < NSUPP; ++e) {
        int idx = row[e];
        int g   = idx & 7;
        int j   = (int)((cur >> (g * 8)) & 0xff);
        cur += 1ull << (g * 8);

        int slot;
        if (j < 8) {
            slot = (((g - c) & 7)) + 8 * j;           // preferred slot
        } else {
            // m-th free-after-pass1 slot (free: k >= min(count[group(t)],8))
            int m = spillrank++;
            slot = 0;
            for (int t = 0; t < NSUPP; ++t) {
                int gg = ((t & 7) + c) & 7;           // group hosted by slot t
                int cg = (int)((cnt >> (gg * 8)) & 0xff);
                if (cg > 8) cg = 8;
                if ((t >> 3) >= cg) {
                    if (m == 0) { slot = t; break; }
                    --m;
                }
            }
        }
        outp[((slot >> 1) * NCLASS + c) * 2 + (slot & 1)] =
            make_int2(idx, __float_as_int(wrow[e]));
    }
}

__global__ void __launch_bounds__(THREADS, 3)
supp_kernel(const float* __restrict__ x, float* __restrict__ out) {
    // One float4 tile: xs[idx] = x[b0..b0+3][idx]. Gather bank group = idx&7,
    // tile-fill STS.128 conflict-free.
    extern __shared__ float4 smem[];
    float4* xs = smem;

    const int b0 = blockIdx.x * NB;

    // --- Stage x tile: 4 rows x 4096 floats = 64 KB ---
    for (int i = threadIdx.x; i < NCHUNK; i += THREADS) {
        const float* xb = x + (size_t)b0 * NCHUNK + i;
        float t0 = xb[0 * NCHUNK];
        float t1 = xb[1 * NCHUNK];
        float t2 = xb[2 * NCHUNK];
        float t3 = xb[3 * NCHUNK];
        xs[i] = make_float4(t0, t1, t2, t3);
    }
    __syncthreads();

    // --- Gather + dot: thread = class (2 per thread), 4 batch rows each ---
    for (int c = threadIdx.x; c < NCLASS; c += THREADS) {
        float a0 = 0.f, a1 = 0.f, a2 = 0.f, a3 = 0.f;
#pragma unroll 4
        for (int s2 = 0; s2 < NSUPP / 2; ++s2) {
            int4 p = g_packed[s2 * NCLASS + c];  // coalesced LDG.128

            float w0 = __int_as_float(p.y);
            float4 v = xs[p.x];
            a0 = fmaf(v.x, w0, a0);
            a1 = fmaf(v.y, w0, a1);
            a2 = fmaf(v.z, w0, a2);
            a3 = fmaf(v.w, w0, a3);

            float w1 = __int_as_float(p.w);
            v = xs[p.z];
            a0 = fmaf(v.x, w1, a0);
            a1 = fmaf(v.y, w1, a1);
            a2 = fmaf(v.z, w1, a2);
            a3 = fmaf(v.w, w1, a3);
        }

        float* o = out + (size_t)b0 * NCLASS + c;
        o[0 * NCLASS] = __expf(a0);
        o[1 * NCLASS] = __expf(a1);
        o[2 * NCLASS] = __expf(a2);
        o[3 * NCLASS] = __expf(a3);
    }
}

extern "C" void kernel_launch(void* const* d_in, const int* in_sizes, int n_in,
                              void* d_out, int out_size) {
    const float* x    = (const float*)d_in[0];  // [4096, 4096] f32
    const float* w    = (const float*)d_in[1];  // [1000, 64]   f32
    const int*   cmap = (const int*)d_in[2];    // [1000, 64]   i32
    float*       out  = (float*)d_out;          // [4096, 1000] f32

    (void)in_sizes; (void)n_in; (void)out_size;

    static const size_t smem_bytes = NCHUNK * sizeof(float4);  // 64 KB
    cudaFuncSetAttribute(supp_kernel,
                         cudaFuncAttributeMaxDynamicSharedMemorySize,
                         (int)smem_bytes);

    pack_kernel<<<(NCLASS + 255) / 256, 256>>>(w, cmap);
    supp_kernel<<<BATCH / NB, THREADS, smem_bytes>>>(x, out);
}

// round 7
// speedup vs baseline: 1.2334x; 1.2334x over previous
#include <cuda_runtime.h>

// out[b,c] = exp( sum_s x[b, chunk_map[c,s]] * wSupp[c,s] )
// B=4096, NCLASS=1000, NSUPP=64, NCHUNK=4096

#define NCLASS 1000
#define NSUPP  64
#define NCHUNK 4096
#define BATCH  4096
#define NB     4       // batch rows per CTA (64 KB tile -> 3 CTAs/SM)
#define THREADS 512

// SoA packed schedule, transposed [chunk][class] for coalesced LDG:
//   g_idx: 8 u16 indices per int4   -> 8 chunks of 8 slots
//   g_w  : 4 f32 weights per float4 -> 16 chunks of 4 slots
// Schedule: slot p of class c prefers an entry with bank group
// (idx&7) == (p + c) & 7, so the 8 lanes of each LDS.128 phase
// (8 consecutive classes) hit 8 distinct bank groups. Overflow entries
// (group count > 8) spill into leftover slots (~13%).
__device__ int4   g_idx[(NSUPP / 8) * NCLASS];
__device__ float4 g_w[(NSUPP / 4) * NCLASS];

// One thread per (class, bank-group): closed-form preferred placement,
// free-slot scan only for rare spill entries. No local arrays.
__global__ void pack_kernel(const float* __restrict__ w,
                            const int* __restrict__ cmap) {
    int t = blockIdx.x * blockDim.x + threadIdx.x;
    if (t >= NCLASS * 8) return;
    int c = t >> 3;
    int g = t & 7;

    const int*   row  = cmap + c * NSUPP;
    const float* wrow = w + c * NSUPP;

    // scan 1: per-group counts, 8x8-bit packed
    unsigned long long cnt = 0ull;
#pragma unroll
    for (int e = 0; e < NSUPP; ++e)
        cnt += 1ull << ((row[e] & 7) * 8);

    unsigned short* idx_out = (unsigned short*)g_idx;
    float*          w_out   = (float*)g_w;

    // scan 2: place entries of group g; track global spill rank
    unsigned long long cur = 0ull;
    int spill_before = 0;
    for (int e = 0; e < NSUPP; ++e) {
        int idx = row[e];
        int gg  = idx & 7;
        int j   = (int)((cur >> (gg * 8)) & 0xff);
        cur += 1ull << (gg * 8);

        if (gg == g) {
            int slot;
            if (j < 8) {
                slot = ((g - c) & 7) + 8 * j;           // preferred slot
            } else {
                // m-th free slot: slot p free iff (p>>3) >= min(cnt[host],8),
                // host group of slot p is ((p&7)+c)&7
                int m = spill_before;
                slot = -1;
                for (int p = 0; p < NSUPP; ++p) {
                    int hg = ((p & 7) + c) & 7;
                    int ch = (int)((cnt >> (hg * 8)) & 0xff);
                    if (ch > 8) ch = 8;
                    if ((p >> 3) >= ch) {
                        if (m == 0) { slot = p; break; }
                        --m;
                    }
                }
            }
            idx_out[((slot >> 3) * NCLASS + c) * 8 + (slot & 7)] =
                (unsigned short)idx;
            w_out[((slot >> 2) * NCLASS + c) * 4 + (slot & 3)] = wrow[e];
        }
        if (j >= 8) ++spill_before;   // global spill ordering (all groups)
    }
}

__global__ void __launch_bounds__(THREADS, 3)
supp_kernel(const float* __restrict__ x, float* __restrict__ out) {
    // xs[idx] = x[b0..b0+3][idx]; gather bank group = idx&7.
    extern __shared__ float4 smem[];
    float4* xs = smem;

    const int b0 = blockIdx.x * NB;

    // --- Stage x tile: 4 rows x 4096 floats = 64 KB ---
    for (int i = threadIdx.x; i < NCHUNK; i += THREADS) {
        const float* xb = x + (size_t)b0 * NCHUNK + i;
        float t0 = xb[0 * NCHUNK];
        float t1 = xb[1 * NCHUNK];
        float t2 = xb[2 * NCHUNK];
        float t3 = xb[3 * NCHUNK];
        xs[i] = make_float4(t0, t1, t2, t3);
    }
    __syncthreads();

    // --- Gather + dot: thread = class (2 per thread), 4 batch rows each ---
    for (int c = threadIdx.x; c < NCLASS; c += THREADS) {
        float a0 = 0.f, a1 = 0.f, a2 = 0.f, a3 = 0.f;
#pragma unroll 2
        for (int k = 0; k < NSUPP / 8; ++k) {       // 8 entries per chunk
            int4   pi = g_idx[k * NCLASS + c];      // 8 u16 idx, LDG.128
            float4 wa = g_w[(2 * k) * NCLASS + c];  // slots 8k..8k+3
            float4 wb = g_w[(2 * k + 1) * NCLASS + c];

            int i0 = pi.x & 0xffff, i1 = ((unsigned)pi.x) >> 16;
            int i2 = pi.y & 0xffff, i3 = ((unsigned)pi.y) >> 16;
            int i4 = pi.z & 0xffff, i5 = ((unsigned)pi.z) >> 16;
            int i6 = pi.w & 0xffff, i7 = ((unsigned)pi.w) >> 16;

            float4 v;
            v = xs[i0]; a0 = fmaf(v.x, wa.x, a0); a1 = fmaf(v.y, wa.x, a1);
                        a2 = fmaf(v.z, wa.x, a2); a3 = fmaf(v.w, wa.x, a3);
            v = xs[i1]; a0 = fmaf(v.x, wa.y, a0); a1 = fmaf(v.y, wa.y, a1);
                        a2 = fmaf(v.z, wa.y, a2); a3 = fmaf(v.w, wa.y, a3);
            v = xs[i2]; a0 = fmaf(v.x, wa.z, a0); a1 = fmaf(v.y, wa.z, a1);
                        a2 = fmaf(v.z, wa.z, a2); a3 = fmaf(v.w, wa.z, a3);
            v = xs[i3]; a0 = fmaf(v.x, wa.w, a0); a1 = fmaf(v.y, wa.w, a1);
                        a2 = fmaf(v.z, wa.w, a2); a3 = fmaf(v.w, wa.w, a3);
            v = xs[i4]; a0 = fmaf(v.x, wb.x, a0); a1 = fmaf(v.y, wb.x, a1);
                        a2 = fmaf(v.z, wb.x, a2); a3 = fmaf(v.w, wb.x, a3);
            v = xs[i5]; a0 = fmaf(v.x, wb.y, a0); a1 = fmaf(v.y, wb.y, a1);
                        a2 = fmaf(v.z, wb.y, a2); a3 = fmaf(v.w, wb.y, a3);
            v = xs[i6]; a0 = fmaf(v.x, wb.z, a0); a1 = fmaf(v.y, wb.z, a1);
                        a2 = fmaf(v.z, wb.z, a2); a3 = fmaf(v.w, wb.z, a3);
            v = xs[i7]; a0 = fmaf(v.x, wb.w, a0); a1 = fmaf(v.y, wb.w, a1);
                        a2 = fmaf(v.z, wb.w, a2); a3 = fmaf(v.w, wb.w, a3);
        }

        float* o = out + (size_t)b0 * NCLASS + c;
        o[0 * NCLASS] = __expf(a0);
        o[1 * NCLASS] = __expf(a1);
        o[2 * NCLASS] = __expf(a2);
        o[3 * NCLASS] = __expf(a3);
    }
}

extern "C" void kernel_launch(void* const* d_in, const int* in_sizes, int n_in,
                              void* d_out, int out_size) {
    const float* x    = (const float*)d_in[0];  // [4096, 4096] f32
    const float* w    = (const float*)d_in[1];  // [1000, 64]   f32
    const int*   cmap = (const int*)d_in[2];    // [1000, 64]   i32
    float*       out  = (float*)d_out;          // [4096, 1000] f32

    (void)in_sizes; (void)n_in; (void)out_size;

    static const size_t smem_bytes = NCHUNK * sizeof(float4);  // 64 KB
    cudaFuncSetAttribute(supp_kernel,
                         cudaFuncAttributeMaxDynamicSharedMemorySize,
                         (int)smem_bytes);

    pack_kernel<<<(NCLASS * 8 + 255) / 256, 256>>>(w, cmap);
    supp_kernel<<<BATCH / NB, THREADS, smem_bytes>>>(x, out);
}

// round 8
// speedup vs baseline: 2.1786x; 1.7663x over previous
#include <cuda_runtime.h>

// out[b,c] = exp( sum_s x[b, chunk_map[c,s]] * wSupp[c,s] )
// B=4096, NCLASS=1000, NSUPP=64, NCHUNK=4096

#define NCLASS 1000
#define NSUPP  64
#define NCHUNK 4096
#define BATCH  4096
#define NB     4       // batch rows per CTA (64 KB tile -> 3 CTAs/SM)
#define THREADS 512

// SoA packed schedule, transposed [chunk][class] for coalesced LDG:
//   g_idx: 8 u16 indices per int4   -> 8 chunks of 8 slots
//   g_w  : 4 f32 weights per float4 -> 16 chunks of 4 slots
// Schedule: slot p of class c prefers an entry with bank group
// (idx&7) == (p + c) & 7, so the 8 lanes of each LDS.128 phase
// (8 consecutive classes) hit 8 distinct bank groups. Overflow entries
// (group count > 8) spill into leftover slots (~13%).
__device__ int4   g_idx[(NSUPP / 8) * NCLASS];
__device__ float4 g_w[(NSUPP / 4) * NCLASS];

// One thread per (class, bank-group). Branch-free: group counts and running
// ranks live in packed 8x8-bit u64 counters; spill slots come from a
// free-slot bitmask popped with ffsll (O(1) per spill, no inner scans).
__global__ void pack_kernel(const float* __restrict__ w,
                            const int* __restrict__ cmap) {
    int t = blockIdx.x * blockDim.x + threadIdx.x;
    if (t >= NCLASS * 8) return;
    int c = t >> 3;
    int g = t & 7;

    const int*   row  = cmap + c * NSUPP;
    const float* wrow = w + c * NSUPP;
    const unsigned long long PRE = 0x0101010101010101ull;

    // pass 1: per-group counts (8 counters x 8 bits in one u64)
    unsigned long long cnt = 0ull;
#pragma unroll 8
    for (int e = 0; e < NSUPP; ++e)
        cnt += 1ull << ((row[e] & 7) * 8);

    // free-slot bitmask: slot p (= residue r, depth k) is free iff
    // k >= min(cnt[hostgroup], 8), hostgroup(r) = (r + c) & 7.
    unsigned long long freemask = 0ull;
#pragma unroll
    for (int r = 0; r < 8; ++r) {
        int hg = (r + c) & 7;
        int ch = (int)((cnt >> (hg * 8)) & 0xff);
        if (ch > 8) ch = 8;
        unsigned long long lowbits =
            (ch >= 8) ? ~0ull : ((1ull << (8 * ch)) - 1ull);
        freemask |= (PRE << r) & ~lowbits;
    }

    unsigned short* idx_out = (unsigned short*)g_idx;
    float*          w_out   = (float*)g_w;

    // pass 2: branch-free placement; spills pop freemask in entry order
    unsigned long long cur = 0ull;
    unsigned long long fm  = freemask;
#pragma unroll 4
    for (int e = 0; e < NSUPP; ++e) {
        int idx = row[e];
        int gg  = idx & 7;
        int j   = (int)((cur >> (gg * 8)) & 0xff);
        cur += 1ull << (gg * 8);

        bool isspill = (j >= 8);
        int pref = ((gg - c) & 7) + 8 * j;          // valid when j < 8
        int sp   = __ffsll((long long)fm) - 1;      // next free slot
        int slot = isspill ? sp : pref;
        fm       = isspill ? (fm & (fm - 1ull)) : fm;

        if (gg == g) {                               // predicated store
            idx_out[((slot >> 3) * NCLASS + c) * 8 + (slot & 7)] =
                (unsigned short)idx;
            w_out[((slot >> 2) * NCLASS + c) * 4 + (slot & 3)] = wrow[e];
        }
    }
}

__global__ void __launch_bounds__(THREADS, 3)
supp_kernel(const float* __restrict__ x, float* __restrict__ out) {
    // xs[idx] = x[b0..b0+3][idx]; gather bank group = idx&7.
    extern __shared__ float4 smem[];
    float4* xs = smem;

    const int b0 = blockIdx.x * NB;

    // --- Stage x tile: 4 rows x 4096 floats = 64 KB ---
    for (int i = threadIdx.x; i < NCHUNK; i += THREADS) {
        const float* xb = x + (size_t)b0 * NCHUNK + i;
        float t0 = xb[0 * NCHUNK];
        float t1 = xb[1 * NCHUNK];
        float t2 = xb[2 * NCHUNK];
        float t3 = xb[3 * NCHUNK];
        xs[i] = make_float4(t0, t1, t2, t3);
    }
    __syncthreads();

    // --- Gather + dot: thread = class (2 per thread), 4 batch rows each ---
    for (int c = threadIdx.x; c < NCLASS; c += THREADS) {
        float a0 = 0.f, a1 = 0.f, a2 = 0.f, a3 = 0.f;
#pragma unroll 2
        for (int k = 0; k < NSUPP / 8; ++k) {       // 8 entries per chunk
            int4   pi = g_idx[k * NCLASS + c];      // 8 u16 idx, LDG.128
            float4 wa = g_w[(2 * k) * NCLASS + c];  // slots 8k..8k+3
            float4 wb = g_w[(2 * k + 1) * NCLASS + c];

            int i0 = pi.x & 0xffff, i1 = ((unsigned)pi.x) >> 16;
            int i2 = pi.y & 0xffff, i3 = ((unsigned)pi.y) >> 16;
            int i4 = pi.z & 0xffff, i5 = ((unsigned)pi.z) >> 16;
            int i6 = pi.w & 0xffff, i7 = ((unsigned)pi.w) >> 16;

            float4 v;
            v = xs[i0]; a0 = fmaf(v.x, wa.x, a0); a1 = fmaf(v.y, wa.x, a1);
                        a2 = fmaf(v.z, wa.x, a2); a3 = fmaf(v.w, wa.x, a3);
            v = xs[i1]; a0 = fmaf(v.x, wa.y, a0); a1 = fmaf(v.y, wa.y, a1);
                        a2 = fmaf(v.z, wa.y, a2); a3 = fmaf(v.w, wa.y, a3);
            v = xs[i2]; a0 = fmaf(v.x, wa.z, a0); a1 = fmaf(v.y, wa.z, a1);
                        a2 = fmaf(v.z, wa.z, a2); a3 = fmaf(v.w, wa.z, a3);
            v = xs[i3]; a0 = fmaf(v.x, wa.w, a0); a1 = fmaf(v.y, wa.w, a1);
                        a2 = fmaf(v.z, wa.w, a2); a3 = fmaf(v.w, wa.w, a3);
            v = xs[i4]; a0 = fmaf(v.x, wb.x, a0); a1 = fmaf(v.y, wb.x, a1);
                        a2 = fmaf(v.z, wb.x, a2); a3 = fmaf(v.w, wb.x, a3);
            v = xs[i5]; a0 = fmaf(v.x, wb.y, a0); a1 = fmaf(v.y, wb.y, a1);
                        a2 = fmaf(v.z, wb.y, a2); a3 = fmaf(v.w, wb.y, a3);
            v = xs[i6]; a0 = fmaf(v.x, wb.z, a0); a1 = fmaf(v.y, wb.z, a1);
                        a2 = fmaf(v.z, wb.z, a2); a3 = fmaf(v.w, wb.z, a3);
            v = xs[i7]; a0 = fmaf(v.x, wb.w, a0); a1 = fmaf(v.y, wb.w, a1);
                        a2 = fmaf(v.z, wb.w, a2); a3 = fmaf(v.w, wb.w, a3);
        }

        float* o = out + (size_t)b0 * NCLASS + c;
        o[0 * NCLASS] = __expf(a0);
        o[1 * NCLASS] = __expf(a1);
        o[2 * NCLASS] = __expf(a2);
        o[3 * NCLASS] = __expf(a3);
    }
}

extern "C" void kernel_launch(void* const* d_in, const int* in_sizes, int n_in,
                              void* d_out, int out_size) {
    const float* x    = (const float*)d_in[0];  // [4096, 4096] f32
    const float* w    = (const float*)d_in[1];  // [1000, 64]   f32
    const int*   cmap = (const int*)d_in[2];    // [1000, 64]   i32
    float*       out  = (float*)d_out;          // [4096, 1000] f32

    (void)in_sizes; (void)n_in; (void)out_size;

    static const size_t smem_bytes = NCHUNK * sizeof(float4);  // 64 KB
    cudaFuncSetAttribute(supp_kernel,
                         cudaFuncAttributeMaxDynamicSharedMemorySize,
                         (int)smem_bytes);

    pack_kernel<<<(NCLASS * 8 + 127) / 128, 128>>>(w, cmap);
    supp_kernel<<<BATCH / NB, THREADS, smem_bytes>>>(x, out);
}